// round 9
// baseline (speedup 1.0000x reference)
#include <cuda_runtime.h>

// TT embedding, binned by full unique id (key = p*50 + i1, p = i2*60+i3).
// vocab = 180000, emb = 512, rank 16, T = 131072 tokens.
//
// Graph (captured with a forked stream):
//   main: memset(g_cnt)->memset(g_total)->k_hist->k_scanA->k_scatter -\
//   s1:   k_build (m23 pair table) ------------------------------------+-> k_compute
//
// scanA uses an atomic block base (no second scan pass); scatter consumes
// g_loc as the running cursor; compute recovers ofs = g_loc[key]-g_cnt[key].

#define NP        3600
#define NKEY      180224          // 704*256
#define NBLK      704
#define C1_ELEMS  6400            // 50*8*16
#define C2_ELEMS  122880          // 60*16*8*16
#define C3_ELEMS  7680            // 60*16*8
#define MAXT      (1 << 18)

__device__ __align__(16) float g_m23[NP * 1024];   // 14.75 MB, L2-resident
__device__ int g_cnt[NKEY];
__device__ int g_loc[NKEY];
__device__ int g_total;
__device__ int g_bin[MAXT];

// ---------------------------------------------------------------------------
// per-block int64-vs-int32 detect: odd 32-bit words of little-endian int64
// ids (< 2^31) are all zero. 256 samples, L2-hit, no global state.
// ---------------------------------------------------------------------------
__device__ __forceinline__ int block_is64(const int* __restrict__ x) {
    __shared__ int s_z;
    if (threadIdx.x == 0) s_z = 0;
    __syncthreads();
    int z = (x[2 * threadIdx.x + 1] == 0) ? 1 : 0;
#pragma unroll
    for (int o = 16; o; o >>= 1) z += __shfl_xor_sync(0xFFFFFFFFu, z, o);
    if ((threadIdx.x & 31) == 0) atomicAdd(&s_z, z);
    __syncthreads();
    return s_z >= 192;
}

// ---------------------------------------------------------------------------
// k_build: m23[p][rh][bc][rl] = sum_s core2[i2][r][b][s]*core3[i3][s][c]
// ---------------------------------------------------------------------------
__global__ void k_build(const float* __restrict__ core2,
                        const float* __restrict__ core3) {
    __shared__ __align__(16) float c2s[2048];   // [r][b][s]
    __shared__ __align__(16) float c3s[128];    // [s][c]
    int p  = blockIdx.x;
    int i2 = p / 60;
    int i3 = p - i2 * 60;
    {
        const float4* g = (const float4*)(core2 + i2 * 2048);
        float4* s = (float4*)c2s;
        for (int i = threadIdx.x; i < 512; i += 128) s[i] = g[i];
        if (threadIdx.x < 32)
            ((float4*)c3s)[threadIdx.x] = ((const float4*)(core3 + i3 * 128))[threadIdx.x];
    }
    __syncthreads();

    int bc  = threadIdx.x & 63;
    int rh2 = threadIdx.x >> 6;                 // r in [rh2*8, rh2*8+8)
    int b   = bc >> 3;
    int c   = bc & 7;
    float v[8];
#pragma unroll
    for (int rr = 0; rr < 8; rr++) {
        const float* c2row = c2s + (rh2 * 8 + rr) * 128 + b * 16;
        float acc = 0.0f;
#pragma unroll
        for (int s = 0; s < 16; s++) acc += c2row[s] * c3s[s * 8 + c];
        v[rr] = acc;
    }
    float* dst = g_m23 + p * 1024;              // [rh][bc][rl]
    *(float4*)(dst + (2 * rh2 + 0) * 256 + bc * 4) = make_float4(v[0], v[1], v[2], v[3]);
    *(float4*)(dst + (2 * rh2 + 1) * 256 + bc * 4) = make_float4(v[4], v[5], v[6], v[7]);
}

// ---------------------------------------------------------------------------
__global__ void k_hist(const int* __restrict__ x, int n) {
    int is64 = block_is64(x);
    int j = blockIdx.x * 256 + threadIdx.x;
    if (j < n) {
        unsigned id = (unsigned)(is64 ? x[2 * j] : x[j]);
        unsigned i1 = id / 3600u;
        unsigned p  = id - i1 * 3600u;
        atomicAdd(&g_cnt[p * 50 + i1], 1);
    }
}

// ---------------------------------------------------------------------------
// scanA: per-block exclusive scan + atomic global base -> absolute offsets.
// ---------------------------------------------------------------------------
__global__ void k_scanA() {                     // NBLK blocks x 256
    __shared__ int s_w[8];
    __shared__ int s_base;
    int lane = threadIdx.x & 31, wid = threadIdx.x >> 5;
    int i = blockIdx.x * 256 + threadIdx.x;
    int v = g_cnt[i];

    int xi = v;
#pragma unroll
    for (int o = 1; o < 32; o <<= 1) {
        int u = __shfl_up_sync(0xFFFFFFFFu, xi, o);
        if (lane >= o) xi += u;
    }
    if (lane == 31) s_w[wid] = xi;
    __syncthreads();
    if (wid == 0) {
        int y = (lane < 8) ? s_w[lane] : 0;
#pragma unroll
        for (int o = 1; o < 8; o <<= 1) {
            int u = __shfl_up_sync(0xFFFFFFFFu, y, o);
            if (lane >= o) y += u;
        }
        if (lane < 8) s_w[lane] = y;
    }
    __syncthreads();
    if (threadIdx.x == 0) s_base = atomicAdd(&g_total, s_w[7]);
    int wbase = wid ? s_w[wid - 1] : 0;
    __syncthreads();
    g_loc[i] = s_base + wbase + xi - v;         // exclusive absolute offset
}

// ---------------------------------------------------------------------------
__global__ void k_scatter(const int* __restrict__ x, int n) {
    int is64 = block_is64(x);
    int j = blockIdx.x * 256 + threadIdx.x;
    if (j < n) {
        unsigned id = (unsigned)(is64 ? x[2 * j] : x[j]);
        unsigned i1 = id / 3600u;
        unsigned p  = id - i1 * 3600u;
        int pos = atomicAdd(&g_loc[p * 50 + i1], 1);
        g_bin[pos] = j;
    }
}

// ---------------------------------------------------------------------------
__device__ __forceinline__ unsigned long long ffma2(unsigned long long a,
                                                    unsigned long long b,
                                                    unsigned long long c) {
    unsigned long long d;
    asm("fma.rn.f32x2 %0, %1, %2, %3;" : "=l"(d) : "l"(a), "l"(b), "l"(c));
    return d;
}

__global__ __launch_bounds__(256, 2)
void k_compute(const float* __restrict__ core1, float* __restrict__ out) {
    __shared__ __align__(16) float  s_g1[C1_ELEMS];   // 25.6 KB  [i1][a][r]
    __shared__ __align__(16) float4 s_m[2][256];      // 8 KB double-buffered

    {
        const float4* g = (const float4*)core1;
        float4* s = (float4*)s_g1;
        for (int i = threadIdx.x; i < C1_ELEMS / 4; i += 256) s[i] = g[i];
    }

    const int lane = threadIdx.x & 31;
    const int w    = threadIdx.x >> 5;
    int buf = 0;

    for (int p = blockIdx.x; p < NP; p += gridDim.x) {
        s_m[buf][threadIdx.x] = ((const float4*)g_m23)[p * 256 + threadIdx.x];
        __syncthreads();                               // covers s_g1 fill on iter 0

        // rows bc = 2*lane (P) and 2*lane+1 (Q), r paired (even,odd)
        unsigned long long Pp[8], Qp[8];
#pragma unroll
        for (int h = 0; h < 4; h++) {
            float4 fp = s_m[buf][h * 64 + 2 * lane];
            float4 fq = s_m[buf][h * 64 + 2 * lane + 1];
            Pp[2 * h]     = *(unsigned long long*)&fp.x;
            Pp[2 * h + 1] = *(unsigned long long*)&fp.z;
            Qp[2 * h]     = *(unsigned long long*)&fq.x;
            Qp[2 * h + 1] = *(unsigned long long*)&fq.z;
        }
        buf ^= 1;

        for (int i1 = w; i1 < 50; i1 += 8) {
            int key = p * 50 + i1;
            int cnt = g_cnt[key];
            if (cnt == 0) continue;
            int ofs = g_loc[key] - cnt;                // scatter advanced g_loc by cnt

            const ulonglong2* g1p = (const ulonglong2*)(s_g1 + i1 * 128);
            float2 o[8];
#pragma unroll
            for (int a = 0; a < 8; a++) {
                ulonglong2 C0 = g1p[a * 4 + 0];
                ulonglong2 C1 = g1p[a * 4 + 1];
                ulonglong2 C2 = g1p[a * 4 + 2];
                ulonglong2 C3 = g1p[a * 4 + 3];

                unsigned long long aP = ffma2(C0.x, Pp[0], 0ull);
                unsigned long long aQ = ffma2(C0.x, Qp[0], 0ull);
                aP = ffma2(C0.y, Pp[1], aP);  aQ = ffma2(C0.y, Qp[1], aQ);
                aP = ffma2(C1.x, Pp[2], aP);  aQ = ffma2(C1.x, Qp[2], aQ);
                aP = ffma2(C1.y, Pp[3], aP);  aQ = ffma2(C1.y, Qp[3], aQ);
                aP = ffma2(C2.x, Pp[4], aP);  aQ = ffma2(C2.x, Qp[4], aQ);
                aP = ffma2(C2.y, Pp[5], aP);  aQ = ffma2(C2.y, Qp[5], aQ);
                aP = ffma2(C3.x, Pp[6], aP);  aQ = ffma2(C3.x, Qp[6], aQ);
                aP = ffma2(C3.y, Pp[7], aP);  aQ = ffma2(C3.y, Qp[7], aQ);

                float2 fP = *(float2*)&aP;
                float2 fQ = *(float2*)&aQ;
                o[a] = make_float2(fP.x + fP.y, fQ.x + fQ.y);
            }

            int j = g_bin[ofs];                        // prefetch-style rotation
            for (int t = 0; t < cnt; t++) {
                int jn = (t + 1 < cnt) ? g_bin[ofs + t + 1] : 0;
                float* op = out + (size_t)j * 512 + 2 * lane;
#pragma unroll
                for (int a = 0; a < 8; a++)
                    __stcs((float2*)(op + a * 64), o[a]);
                j = jn;
            }
        }
    }
}

// ---------------------------------------------------------------------------
extern "C" void kernel_launch(void* const* d_in, const int* in_sizes, int n_in,
                              void* d_out, int out_size) {
    const void*  x  = nullptr;
    const float* c1 = nullptr;
    const float* c2 = nullptr;
    const float* c3 = nullptr;
    int n_tokens = 131072;

    for (int i = 0; i < n_in; i++) {
        switch (in_sizes[i]) {
            case C1_ELEMS: c1 = (const float*)d_in[i]; break;
            case C2_ELEMS: c2 = (const float*)d_in[i]; break;
            case C3_ELEMS: c3 = (const float*)d_in[i]; break;
            default:       x  = d_in[i]; n_tokens = in_sizes[i]; break;
        }
    }

    // lazy one-time setup (runs on the uncaptured correctness call)
    static cudaStream_t s1 = nullptr;
    static cudaEvent_t  evA = nullptr, evB = nullptr;
    static void *p_cnt = nullptr, *p_tot = nullptr;
    if (!s1) {
        cudaStreamCreateWithFlags(&s1, cudaStreamNonBlocking);
        cudaEventCreateWithFlags(&evA, cudaEventDisableTiming);
        cudaEventCreateWithFlags(&evB, cudaEventDisableTiming);
        cudaGetSymbolAddress(&p_cnt, g_cnt);
        cudaGetSymbolAddress(&p_tot, g_total);
    }

    // fork: table build runs concurrently with the binning chain
    cudaEventRecord(evA, 0);
    cudaStreamWaitEvent(s1, evA, 0);
    k_build<<<NP, 128, 0, s1>>>(c2, c3);
    cudaEventRecord(evB, s1);

    cudaMemsetAsync(p_cnt, 0, NKEY * sizeof(int), 0);
    cudaMemsetAsync(p_tot, 0, sizeof(int), 0);
    k_hist   <<<(n_tokens + 255) / 256, 256>>>((const int*)x, n_tokens);
    k_scanA  <<<NBLK, 256>>>();
    k_scatter<<<(n_tokens + 255) / 256, 256>>>((const int*)x, n_tokens);

    cudaStreamWaitEvent(0, evB, 0);               // join table build
    k_compute<<<296, 256>>>(c1, (float*)d_out);
}

// round 12
// speedup vs baseline: 1.0671x; 1.0671x over previous
#include <cuda_runtime.h>

// TT embedding, binned by full unique id (key = p*50 + i1, p = (i2,i3) pair).
// vocab = 50*60*60 = 180000, emb = 512, rank 16, T = 131072 tokens.
//
// Serial launch chain (graph-capturable, no allocs, single stream):
//   k_build   : m23 pair table + zero counters + dtype detect (fused)
//   k_hist    : count tokens per key (4 tokens/thread, MLP over atomics)
//   k_scanA   : per-block exclusive scan + atomic global base (no 2nd pass)
//   k_scatter : bin token indices (4 tokens/thread), bumping g_loc in place
//   k_compute : persistent CTAs over pairs; m23 row in smem/regs; per UNIQUE
//               id one 128-ffma2 contraction, per duplicate only 8 stores.

#define NP        3600
#define NKEY      180224          // 704*256
#define NBLK      704
#define C1_ELEMS  6400            // 50*8*16
#define C2_ELEMS  122880          // 60*16*8*16
#define C3_ELEMS  7680            // 60*16*8
#define MAXT      (1 << 18)

__device__ __align__(16) float g_m23[NP * 1024];   // 14.75 MB, L2-resident
__device__ int g_cnt[NKEY];
__device__ int g_loc[NKEY];
__device__ int g_total;
__device__ int g_bin[MAXT];
__device__ int g_is64;

// ---------------------------------------------------------------------------
// k_build: pair table + zero counters + dtype detect (fused).
// ---------------------------------------------------------------------------
__global__ void k_build(const float* __restrict__ core2,
                        const float* __restrict__ core3,
                        const int* __restrict__ x) {
    __shared__ __align__(16) float c2s[2048];   // [r][b][s]
    __shared__ __align__(16) float c3s[128];    // [s][c]
    int p  = blockIdx.x;
    int gt = p * 128 + threadIdx.x;
    if (gt < NKEY) g_cnt[gt] = 0;
    if (gt == 0) g_total = 0;

    if (p == 0 && threadIdx.x < 32) {           // int64-vs-int32 detect
        int z = 0;
#pragma unroll
        for (int k = 0; k < 4; k++) z += (x[2 * (threadIdx.x + 32 * k) + 1] == 0);
#pragma unroll
        for (int o = 16; o; o >>= 1) z += __shfl_xor_sync(0xFFFFFFFFu, z, o);
        if (threadIdx.x == 0) g_is64 = (z >= 120) ? 1 : 0;
    }

    int i2 = p / 60;
    int i3 = p - i2 * 60;
    {
        const float4* g = (const float4*)(core2 + i2 * 2048);
        float4* s = (float4*)c2s;
        for (int i = threadIdx.x; i < 512; i += 128) s[i] = g[i];
        if (threadIdx.x < 32)
            ((float4*)c3s)[threadIdx.x] = ((const float4*)(core3 + i3 * 128))[threadIdx.x];
    }
    __syncthreads();

    int bc  = threadIdx.x & 63;
    int rh2 = threadIdx.x >> 6;                 // r in [rh2*8, rh2*8+8)
    int b   = bc >> 3;
    int c   = bc & 7;
    float v[8];
#pragma unroll
    for (int rr = 0; rr < 8; rr++) {
        const float* c2row = c2s + (rh2 * 8 + rr) * 128 + b * 16;
        float acc = 0.0f;
#pragma unroll
        for (int s = 0; s < 16; s++) acc += c2row[s] * c3s[s * 8 + c];
        v[rr] = acc;
    }
    // layout: m23[p][rh][bc][rl], rh = r>>2, rl = r&3
    float* dst = g_m23 + p * 1024;
    *(float4*)(dst + (2 * rh2 + 0) * 256 + bc * 4) = make_float4(v[0], v[1], v[2], v[3]);
    *(float4*)(dst + (2 * rh2 + 1) * 256 + bc * 4) = make_float4(v[4], v[5], v[6], v[7]);
}

// ---------------------------------------------------------------------------
// k_hist / k_scatter: 4 tokens per thread for memory-level parallelism over
// the ~318-cycle L2 atomic latency.
// ---------------------------------------------------------------------------
__global__ void k_hist(const int* __restrict__ x, int n) {
    int is64 = g_is64;
    int base = (blockIdx.x * 256 + threadIdx.x) * 4;
    unsigned id[4];
#pragma unroll
    for (int k = 0; k < 4; k++) {
        int j = base + k;
        id[k] = (j < n) ? (unsigned)(is64 ? x[2 * j] : x[j]) : 0xFFFFFFFFu;
    }
#pragma unroll
    for (int k = 0; k < 4; k++) {
        if (id[k] != 0xFFFFFFFFu) {
            unsigned i1 = id[k] / 3600u;
            unsigned p  = id[k] - i1 * 3600u;
            atomicAdd(&g_cnt[p * 50 + i1], 1);
        }
    }
}

// ---------------------------------------------------------------------------
// scanA: per-block exclusive scan + atomic global base -> absolute offsets.
// (bin segment order across blocks is nondeterministic; values are not.)
// ---------------------------------------------------------------------------
__global__ void k_scanA() {                     // NBLK blocks x 256
    __shared__ int s_w[8];
    __shared__ int s_base;
    int lane = threadIdx.x & 31, wid = threadIdx.x >> 5;
    int i = blockIdx.x * 256 + threadIdx.x;
    int v = g_cnt[i];

    int xi = v;
#pragma unroll
    for (int o = 1; o < 32; o <<= 1) {
        int u = __shfl_up_sync(0xFFFFFFFFu, xi, o);
        if (lane >= o) xi += u;
    }
    if (lane == 31) s_w[wid] = xi;
    __syncthreads();
    if (wid == 0 && lane < 8) {
        int y = s_w[lane];
#pragma unroll
        for (int o = 1; o < 8; o <<= 1) {
            int u = __shfl_up_sync(0x000000FFu, y, o);
            if (lane >= o) y += u;
        }
        s_w[lane] = y;
        if (lane == 7) s_base = atomicAdd(&g_total, y);
    }
    __syncthreads();
    int wbase = wid ? s_w[wid - 1] : 0;
    g_loc[i] = s_base + wbase + xi - v;         // exclusive absolute offset
}

// ---------------------------------------------------------------------------
__global__ void k_scatter(const int* __restrict__ x, int n) {
    int is64 = g_is64;
    int base = (blockIdx.x * 256 + threadIdx.x) * 4;
    unsigned id[4];
#pragma unroll
    for (int k = 0; k < 4; k++) {
        int j = base + k;
        id[k] = (j < n) ? (unsigned)(is64 ? x[2 * j] : x[j]) : 0xFFFFFFFFu;
    }
#pragma unroll
    for (int k = 0; k < 4; k++) {
        if (id[k] != 0xFFFFFFFFu) {
            unsigned i1 = id[k] / 3600u;
            unsigned p  = id[k] - i1 * 3600u;
            int pos = atomicAdd(&g_loc[p * 50 + i1], 1);   // bump in place
            g_bin[pos] = base + k;
        }
    }
}

// ---------------------------------------------------------------------------
__device__ __forceinline__ unsigned long long ffma2(unsigned long long a,
                                                    unsigned long long b,
                                                    unsigned long long c) {
    unsigned long long d;
    asm("fma.rn.f32x2 %0, %1, %2, %3;" : "=l"(d) : "l"(a), "l"(b), "l"(c));
    return d;
}

__global__ __launch_bounds__(256, 2)
void k_compute(const float* __restrict__ core1, float* __restrict__ out) {
    __shared__ __align__(16) float  s_g1[C1_ELEMS];   // 25.6 KB  [i1][a][r]
    __shared__ __align__(16) float4 s_m[256];         // 4 KB     [rh][bc]

    {
        const float4* g = (const float4*)core1;
        float4* s = (float4*)s_g1;
        for (int i = threadIdx.x; i < C1_ELEMS / 4; i += 256) s[i] = g[i];
    }

    const int lane = threadIdx.x & 31;
    const int w    = threadIdx.x >> 5;

    for (int p = blockIdx.x; p < NP; p += gridDim.x) {
        __syncthreads();                               // prior pair's reg-loads done
        s_m[threadIdx.x] = ((const float4*)g_m23)[p * 256 + threadIdx.x];
        __syncthreads();

        // rows bc = 2*lane (P) and 2*lane+1 (Q), r paired (even,odd)
        unsigned long long Pp[8], Qp[8];
#pragma unroll
        for (int h = 0; h < 4; h++) {
            float4 fp = s_m[h * 64 + 2 * lane];
            float4 fq = s_m[h * 64 + 2 * lane + 1];
            Pp[2 * h]     = *(unsigned long long*)&fp.x;
            Pp[2 * h + 1] = *(unsigned long long*)&fp.z;
            Qp[2 * h]     = *(unsigned long long*)&fq.x;
            Qp[2 * h + 1] = *(unsigned long long*)&fq.z;
        }

        // warps split the 50 i1 values of this pair
        for (int i1 = w; i1 < 50; i1 += 8) {
            int key = p * 50 + i1;
            int cnt = g_cnt[key];
            if (cnt == 0) continue;
            int ofs = g_loc[key] - cnt;                // scatter advanced g_loc by cnt

            const ulonglong2* g1p = (const ulonglong2*)(s_g1 + i1 * 128);
            float2 o[8];
#pragma unroll
            for (int a = 0; a < 8; a++) {
                ulonglong2 C0 = g1p[a * 4 + 0];
                ulonglong2 C1 = g1p[a * 4 + 1];
                ulonglong2 C2 = g1p[a * 4 + 2];
                ulonglong2 C3 = g1p[a * 4 + 3];

                unsigned long long aP = ffma2(C0.x, Pp[0], 0ull);
                unsigned long long aQ = ffma2(C0.x, Qp[0], 0ull);
                aP = ffma2(C0.y, Pp[1], aP);  aQ = ffma2(C0.y, Qp[1], aQ);
                aP = ffma2(C1.x, Pp[2], aP);  aQ = ffma2(C1.x, Qp[2], aQ);
                aP = ffma2(C1.y, Pp[3], aP);  aQ = ffma2(C1.y, Qp[3], aQ);
                aP = ffma2(C2.x, Pp[4], aP);  aQ = ffma2(C2.x, Qp[4], aQ);
                aP = ffma2(C2.y, Pp[5], aP);  aQ = ffma2(C2.y, Qp[5], aQ);
                aP = ffma2(C3.x, Pp[6], aP);  aQ = ffma2(C3.x, Qp[6], aQ);
                aP = ffma2(C3.y, Pp[7], aP);  aQ = ffma2(C3.y, Qp[7], aQ);

                float2 fP = *(float2*)&aP;
                float2 fQ = *(float2*)&aQ;
                o[a] = make_float2(fP.x + fP.y, fQ.x + fQ.y);
            }

            // replay stores for every duplicate token of this id
            for (int t = 0; t < cnt; t++) {
                int j = g_bin[ofs + t];
                float* op = out + (size_t)j * 512 + 2 * lane;
#pragma unroll
                for (int a = 0; a < 8; a++)
                    __stcs((float2*)(op + a * 64), o[a]);
            }
        }
    }
}

// ---------------------------------------------------------------------------
extern "C" void kernel_launch(void* const* d_in, const int* in_sizes, int n_in,
                              void* d_out, int out_size) {
    const void*  x  = nullptr;
    const float* c1 = nullptr;
    const float* c2 = nullptr;
    const float* c3 = nullptr;
    int n_tokens = 131072;

    for (int i = 0; i < n_in; i++) {
        switch (in_sizes[i]) {
            case C1_ELEMS: c1 = (const float*)d_in[i]; break;
            case C2_ELEMS: c2 = (const float*)d_in[i]; break;
            case C3_ELEMS: c3 = (const float*)d_in[i]; break;
            default:       x  = d_in[i]; n_tokens = in_sizes[i]; break;
        }
    }

    int tb4 = (n_tokens + 1023) / 1024;        // 4 tokens per thread
    k_build  <<<NP, 128>>>(c2, c3, (const int*)x);
    k_hist   <<<tb4, 256>>>((const int*)x, n_tokens);
    k_scanA  <<<NBLK, 256>>>();
    k_scatter<<<tb4, 256>>>((const int*)x, n_tokens);
    k_compute<<<296, 256>>>(c1, (float*)d_out);
}

// round 13
// speedup vs baseline: 1.0720x; 1.0046x over previous
#include <cuda_runtime.h>

// TT embedding, binned by full unique id (key = p*50 + i1, p = (i2,i3) pair).
// vocab = 50*60*60 = 180000, emb = 512, rank 16, T = 131072 tokens.
//
// Serial launch chain (graph-capturable, no allocs, single stream):
//   k_build   : m23 pair table + zero counters + dtype detect (fused)
//   k_hist    : count tokens per key (4 tokens/thread, MLP over atomics)
//   k_scanA   : per-block exclusive scan + atomic global base (no 2nd pass)
//   k_scatter : bin token indices (4 tokens/thread), bumping g_loc in place
//   k_compute : persistent CTAs over pairs; m23 row in smem/regs; per UNIQUE
//               id one 128-ffma2 contraction, per duplicate only 8 stores.

#define NP        3600
#define NKEY      180224          // 704*256
#define NBLK      704
#define C1_ELEMS  6400            // 50*8*16
#define C2_ELEMS  122880          // 60*16*8*16
#define C3_ELEMS  7680            // 60*16*8
#define MAXT      (1 << 18)

__device__ __align__(16) float g_m23[NP * 1024];   // 14.75 MB, L2-resident
__device__ int g_cnt[NKEY];
__device__ int g_loc[NKEY];
__device__ int g_total;
__device__ int g_bin[MAXT];
__device__ int g_is64;

// ---------------------------------------------------------------------------
// k_build: pair table + zero counters + dtype detect (fused).
// ---------------------------------------------------------------------------
__global__ void k_build(const float* __restrict__ core2,
                        const float* __restrict__ core3,
                        const int* __restrict__ x) {
    __shared__ __align__(16) float c2s[2048];   // [r][b][s]
    __shared__ __align__(16) float c3s[128];    // [s][c]
    int p  = blockIdx.x;
    int gt = p * 128 + threadIdx.x;
    if (gt < NKEY) g_cnt[gt] = 0;
    if (gt == 0) g_total = 0;

    if (p == 0 && threadIdx.x < 32) {           // int64-vs-int32 detect
        int z = 0;
#pragma unroll
        for (int k = 0; k < 4; k++) z += (x[2 * (threadIdx.x + 32 * k) + 1] == 0);
#pragma unroll
        for (int o = 16; o; o >>= 1) z += __shfl_xor_sync(0xFFFFFFFFu, z, o);
        if (threadIdx.x == 0) g_is64 = (z >= 120) ? 1 : 0;
    }

    int i2 = p / 60;
    int i3 = p - i2 * 60;
    {
        const float4* g = (const float4*)(core2 + i2 * 2048);
        float4* s = (float4*)c2s;
        for (int i = threadIdx.x; i < 512; i += 128) s[i] = g[i];
        if (threadIdx.x < 32)
            ((float4*)c3s)[threadIdx.x] = ((const float4*)(core3 + i3 * 128))[threadIdx.x];
    }
    __syncthreads();

    int bc  = threadIdx.x & 63;
    int rh2 = threadIdx.x >> 6;                 // r in [rh2*8, rh2*8+8)
    int b   = bc >> 3;
    int c   = bc & 7;
    float v[8];
#pragma unroll
    for (int rr = 0; rr < 8; rr++) {
        const float* c2row = c2s + (rh2 * 8 + rr) * 128 + b * 16;
        float acc = 0.0f;
#pragma unroll
        for (int s = 0; s < 16; s++) acc += c2row[s] * c3s[s * 8 + c];
        v[rr] = acc;
    }
    // layout: m23[p][rh][bc][rl], rh = r>>2, rl = r&3
    float* dst = g_m23 + p * 1024;
    *(float4*)(dst + (2 * rh2 + 0) * 256 + bc * 4) = make_float4(v[0], v[1], v[2], v[3]);
    *(float4*)(dst + (2 * rh2 + 1) * 256 + bc * 4) = make_float4(v[4], v[5], v[6], v[7]);
}

// ---------------------------------------------------------------------------
// k_hist / k_scatter: 4 tokens per thread for memory-level parallelism over
// the ~318-cycle L2 atomic latency.
// ---------------------------------------------------------------------------
__global__ void k_hist(const int* __restrict__ x, int n) {
    int is64 = g_is64;
    int base = (blockIdx.x * 256 + threadIdx.x) * 4;
    unsigned id[4];
#pragma unroll
    for (int k = 0; k < 4; k++) {
        int j = base + k;
        id[k] = (j < n) ? (unsigned)(is64 ? x[2 * j] : x[j]) : 0xFFFFFFFFu;
    }
#pragma unroll
    for (int k = 0; k < 4; k++) {
        if (id[k] != 0xFFFFFFFFu) {
            unsigned i1 = id[k] / 3600u;
            unsigned p  = id[k] - i1 * 3600u;
            atomicAdd(&g_cnt[p * 50 + i1], 1);
        }
    }
}

// ---------------------------------------------------------------------------
// scanA: per-block exclusive scan + atomic global base -> absolute offsets.
// (bin segment order across blocks is nondeterministic; values are not.)
// ---------------------------------------------------------------------------
__global__ void k_scanA() {                     // NBLK blocks x 256
    __shared__ int s_w[8];
    __shared__ int s_base;
    int lane = threadIdx.x & 31, wid = threadIdx.x >> 5;
    int i = blockIdx.x * 256 + threadIdx.x;
    int v = g_cnt[i];

    int xi = v;
#pragma unroll
    for (int o = 1; o < 32; o <<= 1) {
        int u = __shfl_up_sync(0xFFFFFFFFu, xi, o);
        if (lane >= o) xi += u;
    }
    if (lane == 31) s_w[wid] = xi;
    __syncthreads();
    if (wid == 0 && lane < 8) {
        int y = s_w[lane];
#pragma unroll
        for (int o = 1; o < 8; o <<= 1) {
            int u = __shfl_up_sync(0x000000FFu, y, o);
            if (lane >= o) y += u;
        }
        s_w[lane] = y;
        if (lane == 7) s_base = atomicAdd(&g_total, y);
    }
    __syncthreads();
    int wbase = wid ? s_w[wid - 1] : 0;
    g_loc[i] = s_base + wbase + xi - v;         // exclusive absolute offset
}

// ---------------------------------------------------------------------------
__global__ void k_scatter(const int* __restrict__ x, int n) {
    int is64 = g_is64;
    int base = (blockIdx.x * 256 + threadIdx.x) * 4;
    unsigned id[4];
#pragma unroll
    for (int k = 0; k < 4; k++) {
        int j = base + k;
        id[k] = (j < n) ? (unsigned)(is64 ? x[2 * j] : x[j]) : 0xFFFFFFFFu;
    }
#pragma unroll
    for (int k = 0; k < 4; k++) {
        if (id[k] != 0xFFFFFFFFu) {
            unsigned i1 = id[k] / 3600u;
            unsigned p  = id[k] - i1 * 3600u;
            int pos = atomicAdd(&g_loc[p * 50 + i1], 1);   // bump in place
            g_bin[pos] = base + k;
        }
    }
}

// ---------------------------------------------------------------------------
__device__ __forceinline__ unsigned long long ffma2(unsigned long long a,
                                                    unsigned long long b,
                                                    unsigned long long c) {
    unsigned long long d;
    asm("fma.rn.f32x2 %0, %1, %2, %3;" : "=l"(d) : "l"(a), "l"(b), "l"(c));
    return d;
}

__global__ __launch_bounds__(256, 2)
void k_compute(const float* __restrict__ core1, float* __restrict__ out) {
    __shared__ __align__(16) float  s_g1[C1_ELEMS];   // 25.6 KB  [i1][a][r]
    __shared__ __align__(16) float4 s_m[256];         // 4 KB     [rh][bc]

    {
        const float4* g = (const float4*)core1;
        float4* s = (float4*)s_g1;
        for (int i = threadIdx.x; i < C1_ELEMS / 4; i += 256) s[i] = g[i];
    }

    const int lane = threadIdx.x & 31;
    const int w    = threadIdx.x >> 5;

    for (int p = blockIdx.x; p < NP; p += gridDim.x) {
        __syncthreads();                               // prior pair's reg-loads done
        s_m[threadIdx.x] = ((const float4*)g_m23)[p * 256 + threadIdx.x];
        __syncthreads();

        // rows bc = 2*lane (P) and 2*lane+1 (Q), r paired (even,odd)
        unsigned long long Pp[8], Qp[8];
#pragma unroll
        for (int h = 0; h < 4; h++) {
            float4 fp = s_m[h * 64 + 2 * lane];
            float4 fq = s_m[h * 64 + 2 * lane + 1];
            Pp[2 * h]     = *(unsigned long long*)&fp.x;
            Pp[2 * h + 1] = *(unsigned long long*)&fp.z;
            Qp[2 * h]     = *(unsigned long long*)&fq.x;
            Qp[2 * h + 1] = *(unsigned long long*)&fq.z;
        }

        // warps split the 50 i1 values of this pair
        for (int i1 = w; i1 < 50; i1 += 8) {
            int key = p * 50 + i1;
            int cnt = g_cnt[key];
            if (cnt == 0) continue;
            int ofs = g_loc[key] - cnt;                // scatter advanced g_loc by cnt

            const ulonglong2* g1p = (const ulonglong2*)(s_g1 + i1 * 128);
            float2 o[8];
#pragma unroll
            for (int a = 0; a < 8; a++) {
                ulonglong2 C0 = g1p[a * 4 + 0];
                ulonglong2 C1 = g1p[a * 4 + 1];
                ulonglong2 C2 = g1p[a * 4 + 2];
                ulonglong2 C3 = g1p[a * 4 + 3];

                unsigned long long aP = ffma2(C0.x, Pp[0], 0ull);
                unsigned long long aQ = ffma2(C0.x, Qp[0], 0ull);
                aP = ffma2(C0.y, Pp[1], aP);  aQ = ffma2(C0.y, Qp[1], aQ);
                aP = ffma2(C1.x, Pp[2], aP);  aQ = ffma2(C1.x, Qp[2], aQ);
                aP = ffma2(C1.y, Pp[3], aP);  aQ = ffma2(C1.y, Qp[3], aQ);
                aP = ffma2(C2.x, Pp[4], aP);  aQ = ffma2(C2.x, Qp[4], aQ);
                aP = ffma2(C2.y, Pp[5], aP);  aQ = ffma2(C2.y, Qp[5], aQ);
                aP = ffma2(C3.x, Pp[6], aP);  aQ = ffma2(C3.x, Qp[6], aQ);
                aP = ffma2(C3.y, Pp[7], aP);  aQ = ffma2(C3.y, Qp[7], aQ);

                float2 fP = *(float2*)&aP;
                float2 fQ = *(float2*)&aQ;
                o[a] = make_float2(fP.x + fP.y, fQ.x + fQ.y);
            }

            // replay stores for every duplicate token of this id
            for (int t = 0; t < cnt; t++) {
                int j = g_bin[ofs + t];
                float* op = out + (size_t)j * 512 + 2 * lane;
#pragma unroll
                for (int a = 0; a < 8; a++)
                    __stcs((float2*)(op + a * 64), o[a]);
            }
        }
    }
}

// ---------------------------------------------------------------------------
extern "C" void kernel_launch(void* const* d_in, const int* in_sizes, int n_in,
                              void* d_out, int out_size) {
    const void*  x  = nullptr;
    const float* c1 = nullptr;
    const float* c2 = nullptr;
    const float* c3 = nullptr;
    int n_tokens = 131072;

    for (int i = 0; i < n_in; i++) {
        switch (in_sizes[i]) {
            case C1_ELEMS: c1 = (const float*)d_in[i]; break;
            case C2_ELEMS: c2 = (const float*)d_in[i]; break;
            case C3_ELEMS: c3 = (const float*)d_in[i]; break;
            default:       x  = d_in[i]; n_tokens = in_sizes[i]; break;
        }
    }

    int tb4 = (n_tokens + 1023) / 1024;        // 4 tokens per thread
    k_build  <<<NP, 128>>>(c2, c3, (const int*)x);
    k_hist   <<<tb4, 256>>>((const int*)x, n_tokens);
    k_scanA  <<<NBLK, 256>>>();
    k_scatter<<<tb4, 256>>>((const int*)x, n_tokens);
    k_compute<<<296, 256>>>(c1, (float*)d_out);
}